// round 9
// baseline (speedup 1.0000x reference)
#include <cuda_runtime.h>
#include <cuda_bf16.h>
#include <math.h>
#include <stdint.h>

#define NROWS 65536
#define DIM   512
#define KCLS  512
#define LISTCAP 768

// -------- scratch (device globals; no runtime allocation) --------
__device__ __nv_bfloat16  g_embh[(size_t)NROWS * DIM];   // normalized embeddings bf16
__device__ float          g_sums[KCLS * DIM];            // per-class sums (fp32, atomic)
__device__ __nv_bfloat16  g_centh[KCLS * DIM];           // centroids bf16 (GEMM B)
__device__ float          g_cnt[KCLS];
__device__ float          g_snorm2[KCLS];
__device__ int            g_ccount[KCLS];
__device__ int            g_lists[KCLS * LISTCAP];

// ================= helpers =================
__device__ __forceinline__ uint32_t smem_u32(const void* p) {
    uint32_t a;
    asm("{ .reg .u64 t; cvta.to.shared.u64 t, %1; cvt.u32.u64 %0, t; }" : "=r"(a) : "l"(p));
    return a;
}
#define CP16(dst, src)  asm volatile("cp.async.cg.shared.global [%0], [%1], 16;" :: "r"(dst), "l"(src) : "memory")
#define CP_COMMIT()     asm volatile("cp.async.commit_group;" ::: "memory")
#define CP_WAIT0()      asm volatile("cp.async.wait_group 0;" ::: "memory")
#define CP_WAIT1()      asm volatile("cp.async.wait_group 1;" ::: "memory")

#define LDSM4(r0, r1, r2, r3, addr)                                           \
    asm volatile("ldmatrix.sync.aligned.m8n8.x4.shared.b16 {%0,%1,%2,%3}, [%4];" \
        : "=r"(r0), "=r"(r1), "=r"(r2), "=r"(r3) : "r"(addr))

#define MMA16816(c, a, b0, b1)                                                \
    asm volatile("mma.sync.aligned.m16n8k16.row.col.f32.bf16.bf16.f32 "       \
        "{%0,%1,%2,%3}, {%4,%5,%6,%7}, {%8,%9}, {%0,%1,%2,%3};"               \
        : "+f"((c)[0]), "+f"((c)[1]), "+f"((c)[2]), "+f"((c)[3])              \
        : "r"((a)[0]), "r"((a)[1]), "r"((a)[2]), "r"((a)[3]), "r"(b0), "r"(b1))

__device__ __forceinline__ float2 bf2f(uint32_t u) {
    __nv_bfloat162 h = *(__nv_bfloat162*)&u;
    return __bfloat1622float2(h);
}

// ================= prep kernels =================
__global__ void k_zero(float* out) {
    int t = blockIdx.x * blockDim.x + threadIdx.x;
    if (t < KCLS * DIM) g_sums[t] = 0.0f;
    if (t < KCLS) g_ccount[t] = 0;
    if (t == 0) out[0] = 0.0f;
}

// normalize rows -> bf16, and append row to its class list (fused k_lists)
__global__ void k_norm(const float* __restrict__ x, const int* __restrict__ labels) {
    int row  = blockIdx.x * 8 + (threadIdx.x >> 5);
    int lane = threadIdx.x & 31;
    const float4* src = (const float4*)(x + (size_t)row * DIM);
    float4 v[4];
    float ss = 0.0f;
#pragma unroll
    for (int q = 0; q < 4; q++) {
        v[q] = src[lane + 32 * q];
        ss += v[q].x * v[q].x + v[q].y * v[q].y + v[q].z * v[q].z + v[q].w * v[q].w;
    }
#pragma unroll
    for (int o = 16; o >= 1; o >>= 1) ss += __shfl_xor_sync(0xffffffffu, ss, o);
    float inv = 1.0f / fmaxf(sqrtf(ss), 1e-12f);
    __nv_bfloat162* dsth = (__nv_bfloat162*)(g_embh + (size_t)row * DIM);
#pragma unroll
    for (int q = 0; q < 4; q++) {
        float4 w = v[q];
        w.x *= inv; w.y *= inv; w.z *= inv; w.w *= inv;
        int i = lane + 32 * q;
        dsth[2 * i]     = __floats2bfloat162_rn(w.x, w.y);
        dsth[2 * i + 1] = __floats2bfloat162_rn(w.z, w.w);
    }
    if (lane == 0) {
        int lab = labels[row];
        int pos = atomicAdd(&g_ccount[lab], 1);
        if (pos < LISTCAP) g_lists[lab * LISTCAP + pos] = row;
    }
}

// class partial sums: grid (KCLS, 8 segments), bf16 gather + fp32 atomics
__global__ void k_csum_part() {
    __shared__ int lst_s[LISTCAP / 8 + 8];
    const int k   = blockIdx.x;
    const int seg = blockIdx.y;
    const int t   = threadIdx.x;              // dims 2t, 2t+1
    const int cnt = g_ccount[k];
    const int s0 = (cnt * seg) >> 3;
    const int s1 = (cnt * (seg + 1)) >> 3;
    const int len = s1 - s0;
    const int* lst = g_lists + k * LISTCAP + s0;
    for (int i = t; i < len; i += 256) lst_s[i] = lst[i];
    __syncthreads();

    float a0 = 0.0f, a1 = 0.0f;
    int m = 0;
    for (; m + 8 <= len; m += 8) {
        uint32_t u[8];
#pragma unroll
        for (int j = 0; j < 8; j++)
            u[j] = *(const uint32_t*)(g_embh + (size_t)lst_s[m + j] * DIM + 2 * t);
#pragma unroll
        for (int j = 0; j < 8; j++) {
            float2 f = bf2f(u[j]);
            a0 += f.x; a1 += f.y;
        }
    }
    for (; m < len; m++) {
        float2 f = bf2f(*(const uint32_t*)(g_embh + (size_t)lst_s[m] * DIM + 2 * t));
        a0 += f.x; a1 += f.y;
    }
    if (len > 0) {
        atomicAdd(&g_sums[k * DIM + 2 * t], a0);
        atomicAdd(&g_sums[k * DIM + 2 * t + 1], a1);
    }
}

// finalize: centroids bf16, counts, ||s||^2
__global__ void k_cfin() {
    int k = blockIdx.x;
    int t = threadIdx.x;
    float a0 = g_sums[k * DIM + t];
    float a1 = g_sums[k * DIM + t + 256];
    float c = (float)g_ccount[k];
    if (t == 0) g_cnt[k] = c;
    float inv = 1.0f / fmaxf(c, 1.0f);
    g_centh[k * DIM + t]       = __float2bfloat16(a0 * inv);
    g_centh[k * DIM + t + 256] = __float2bfloat16(a1 * inv);

    __shared__ float red[256];
    red[t] = a0 * a0 + a1 * a1;
    __syncthreads();
    for (int s = 128; s > 0; s >>= 1) {
        if (t < s) red[t] += red[t + s];
        __syncthreads();
    }
    if (t == 0) g_snorm2[k] = red[0];
}

// ================= main: bf16 mma.sync GEMM + fused LSE + inline own-logit =================
// dyn smem: [0, 128K) resident A; [128K, 128K+3*16K) B ring; [176K, +512) rowOwn
#define SM_B_OFF   131072
#define SM_OWN_OFF (131072 + 3 * 16384)
#define SMEM_BYTES (SM_OWN_OFF + 1024)

// B stage loader: stage s covers classes (s>>3)*128.., k-offset (s&7)*64..
__device__ __forceinline__ void load_stage_fn(uint32_t smB, int tid, int s) {
    const uint32_t base = smB + (uint32_t)(s % 3) * 16384;
    const int c0 = (s >> 3) * 128;
    const int k0 = (s & 7) * 64;
#pragma unroll
    for (int it = 0; it < 4; it++) {
        uint32_t u = it * 256 + tid;
        uint32_t nr = u >> 3, k16 = u & 7;
        CP16(base + nr * 128 + ((k16 ^ (nr & 7)) << 4),
             g_centh + (size_t)(c0 + nr) * DIM + k0 + k16 * 8);
    }
    CP_COMMIT();
}

__global__ void __launch_bounds__(256, 1)
k_main_mma(const int* __restrict__ labels,
           const float* __restrict__ wp, const float* __restrict__ bp,
           float* __restrict__ out) {
    extern __shared__ char smem[];
    const uint32_t smA = smem_u32(smem);
    const uint32_t smB = smA + SM_B_OFF;
    float* rowOwn = (float*)(smem + SM_OWN_OFF);

    const int tid = threadIdx.x;
    const int wid = tid >> 5;
    const int l   = tid & 31;
    const int wm  = wid >> 1;        // 0..3 (M)
    const int wn  = wid & 1;         // 0..1 (N half)
    const int block_row = blockIdx.x * 128;

    const float wv = fmaxf(wp[0], 1e-6f);
    const float bv = bp[0];

    // ---- resident A tile (128 x 512 bf16), one cp.async group ----
#pragma unroll
    for (int it = 0; it < 32; it++) {
        uint32_t u = it * 256 + tid;
        uint32_t r = u >> 6, ch = u & 63;
        CP16(smA + r * 1024 + ((ch ^ (r & 7)) << 4),
             g_embh + (size_t)(block_row + r) * DIM + ch * 8);
    }
    CP_COMMIT();

    // ---- per-thread row metadata ----
    int   lab_[2][2];
    float cnt_[2][2], sn_[2][2];
#pragma unroll
    for (int mt = 0; mt < 2; mt++)
#pragma unroll
        for (int h = 0; h < 2; h++) {
            int rr = block_row + wm * 32 + mt * 16 + (l >> 2) + h * 8;
            int lb = labels[rr];
            lab_[mt][h] = lb;
            cnt_[mt][h] = g_cnt[lb];
            sn_[mt][h]  = g_snorm2[lb];
        }

    float run_m[2][2], run_s[2][2];
#pragma unroll
    for (int mt = 0; mt < 2; mt++)
#pragma unroll
        for (int h = 0; h < 2; h++) { run_m[mt][h] = -INFINITY; run_s[mt][h] = 0.0f; }

    load_stage_fn(smB, tid, 0);
    load_stage_fn(smB, tid, 1);

    float acc[2][8][4];
#pragma unroll
    for (int mt = 0; mt < 2; mt++)
#pragma unroll
        for (int nt = 0; nt < 8; nt++)
#pragma unroll
            for (int c = 0; c < 4; c++) acc[mt][nt][c] = 0.0f;

    for (int s = 0; s < 32; s++) {
        // stage s ready (allow 1 younger group in flight)
        if (s < 31) CP_WAIT1(); else CP_WAIT0();
        __syncthreads();                       // data visible + prev stage buffer free
        if (s + 2 < 32) load_stage_fn(smB, tid, s + 2);  // overwrites stage s-1 buffer (done)

        const uint32_t bbase = smB + (uint32_t)(s % 3) * 16384;
        const int kb = s & 7;

#pragma unroll
        for (int step = 0; step < 4; step++) {
            uint32_t a[2][4];
#pragma unroll
            for (int mt = 0; mt < 2; mt++) {
                uint32_t r = wm * 32 + mt * 16 + (l & 15);
                uint32_t chA = kb * 8 + step * 2 + (l >> 4);
                LDSM4(a[mt][0], a[mt][1], a[mt][2], a[mt][3],
                      smA + r * 1024 + ((chA ^ (r & 7)) << 4));
            }
            uint32_t bf[8][2];
#pragma unroll
            for (int np = 0; np < 4; np++) {
                uint32_t n = wn * 64 + np * 16 + (l & 7) + ((l >> 4) & 1) * 8;
                uint32_t chB = step * 2 + ((l >> 3) & 1);
                uint32_t r0, r1, r2, r3;
                LDSM4(r0, r1, r2, r3, bbase + n * 128 + ((chB ^ (n & 7)) << 4));
                bf[2 * np][0] = r0;     bf[2 * np][1] = r1;
                bf[2 * np + 1][0] = r2; bf[2 * np + 1][1] = r3;
            }
#pragma unroll
            for (int mt = 0; mt < 2; mt++)
#pragma unroll
                for (int nt = 0; nt < 8; nt++)
                    MMA16816(acc[mt][nt], a[mt], bf[nt][0], bf[nt][1]);
        }
        __syncthreads();                       // all warps done reading stage s

        if (kb == 7) {
            // ---- chunk epilogue: per-row LSE over this warp's 64 cols ----
            const int c0 = (s >> 3) * 128;
#pragma unroll
            for (int mt = 0; mt < 2; mt++) {
#pragma unroll
                for (int h = 0; h < 2; h++) {
                    const int lb = lab_[mt][h];
                    float v[16];
                    float cm = -INFINITY;
#pragma unroll
                    for (int nt = 0; nt < 8; nt++)
#pragma unroll
                        for (int cc = 0; cc < 2; cc++) {
                            int col = c0 + wn * 64 + nt * 8 + ((l & 3) << 1) + cc;
                            float raw = acc[mt][nt][h * 2 + cc];
                            float lg;
                            if (col == lb) {
                                float cnt = cnt_[mt][h];
                                if (cnt > 1.0f) {
                                    float tt = raw * cnt;          // e . sums[lab]
                                    float denom = cnt - 1.0f;
                                    float num = (tt - 1.0f) / denom;
                                    float nrm = sqrtf(fmaxf(sn_[mt][h] - 2.0f * tt + 1.0f, 0.0f)) / denom;
                                    lg = fmaf(wv, num / fmaxf(nrm, 1e-12f), bv);
                                } else {
                                    lg = fmaf(wv, raw, bv);        // singleton: keep cur
                                }
                                rowOwn[wm * 32 + mt * 16 + h * 8 + (l >> 2)] = lg;
                            } else {
                                lg = fmaf(wv, raw, bv);
                            }
                            v[nt * 2 + cc] = lg;
                            cm = fmaxf(cm, lg);
                        }
#pragma unroll
                    for (int o = 1; o <= 2; o <<= 1)
                        cm = fmaxf(cm, __shfl_xor_sync(0xffffffffu, cm, o));
                    float cs = 0.0f;
#pragma unroll
                    for (int j = 0; j < 16; j++) cs += __expf(v[j] - cm);
#pragma unroll
                    for (int o = 1; o <= 2; o <<= 1)
                        cs += __shfl_xor_sync(0xffffffffu, cs, o);
                    float mo = run_m[mt][h];
                    float mn = fmaxf(mo, cm);
                    run_s[mt][h] = run_s[mt][h] * __expf(mo - mn) + cs * __expf(cm - mn);
                    run_m[mt][h] = mn;
                }
            }
            // re-zero accumulators for next chunk
#pragma unroll
            for (int mt = 0; mt < 2; mt++)
#pragma unroll
                for (int nt = 0; nt < 8; nt++)
#pragma unroll
                    for (int c = 0; c < 4; c++) acc[mt][nt][c] = 0.0f;
        }
    }

    // ---- merge the two N-half warps per row, compute loss ----
    __syncthreads();
    float* marr = (float*)smem;          // reuse A region (dead now)
    float* sarr = marr + 128;
    if (wn == 0 && (l & 3) == 0) {
#pragma unroll
        for (int mt = 0; mt < 2; mt++)
#pragma unroll
            for (int h = 0; h < 2; h++) {
                int rr = wm * 32 + mt * 16 + h * 8 + (l >> 2);
                marr[rr] = run_m[mt][h];
                sarr[rr] = run_s[mt][h];
            }
    }
    __syncthreads();
    float loss = 0.0f;
    if (wn == 1 && (l & 3) == 0) {
#pragma unroll
        for (int mt = 0; mt < 2; mt++)
#pragma unroll
            for (int h = 0; h < 2; h++) {
                int rr = wm * 32 + mt * 16 + h * 8 + (l >> 2);
                float m0 = marr[rr], s0 = sarr[rr];
                float m1 = run_m[mt][h], s1 = run_s[mt][h];
                float mn = fmaxf(m0, m1);
                float ssum = s0 * __expf(m0 - mn) + s1 * __expf(m1 - mn);
                loss += mn + logf(ssum) - rowOwn[rr];
            }
    }
#pragma unroll
    for (int o = 16; o >= 1; o >>= 1) loss += __shfl_xor_sync(0xffffffffu, loss, o);
    if (wn == 1 && l == 0) atomicAdd(out, loss * (1.0f / (float)NROWS));
}

extern "C" void kernel_launch(void* const* d_in, const int* in_sizes, int n_in,
                              void* d_out, int out_size) {
    const float* emb    = (const float*)d_in[0];
    const int*   labels = (const int*)d_in[1];
    const float* wp     = (const float*)d_in[2];
    const float* bp     = (const float*)d_in[3];
    float* out = (float*)d_out;

    cudaFuncSetAttribute(k_main_mma, cudaFuncAttributeMaxDynamicSharedMemorySize, SMEM_BYTES);

    k_zero<<<(KCLS * DIM) / 256, 256>>>(out);
    k_norm<<<NROWS / 8, 256>>>(emb, labels);
    k_csum_part<<<dim3(KCLS, 8), 256>>>();
    k_cfin<<<KCLS, 256>>>();
    k_main_mma<<<NROWS / 128, 256, SMEM_BYTES>>>(labels, wp, bp, out);
}

// round 13
// speedup vs baseline: 1.0012x; 1.0012x over previous
#include <cuda_runtime.h>
#include <cuda_bf16.h>
#include <math.h>
#include <stdint.h>

#define NROWS 65536
#define DIM   512
#define KCLS  512
#define LISTCAP 768

// -------- scratch (device globals; no runtime allocation) --------
__device__ __nv_bfloat16  g_embh[(size_t)NROWS * DIM];   // normalized embeddings bf16
__device__ float          g_sums[KCLS * DIM];            // per-class sums (fp32, atomic)
__device__ __nv_bfloat16  g_centh[KCLS * DIM];           // centroids bf16 (GEMM B)
__device__ float          g_cnt[KCLS];
__device__ float          g_snorm2[KCLS];
__device__ int            g_ccount[KCLS];
__device__ int            g_lists[KCLS * LISTCAP];

// ================= helpers =================
__device__ __forceinline__ uint32_t smem_u32(const void* p) {
    uint32_t a;
    asm("{ .reg .u64 t; cvta.to.shared.u64 t, %1; cvt.u32.u64 %0, t; }" : "=r"(a) : "l"(p));
    return a;
}
#define CP16(dst, src)  asm volatile("cp.async.cg.shared.global [%0], [%1], 16;" :: "r"(dst), "l"(src) : "memory")
#define CP_COMMIT()     asm volatile("cp.async.commit_group;" ::: "memory")
#define CP_WAIT0()      asm volatile("cp.async.wait_group 0;" ::: "memory")
#define CP_WAIT1()      asm volatile("cp.async.wait_group 1;" ::: "memory")

#define LDSM4(r0, r1, r2, r3, addr)                                           \
    asm volatile("ldmatrix.sync.aligned.m8n8.x4.shared.b16 {%0,%1,%2,%3}, [%4];" \
        : "=r"(r0), "=r"(r1), "=r"(r2), "=r"(r3) : "r"(addr))

#define MMA16816(c, a, b0, b1)                                                \
    asm volatile("mma.sync.aligned.m16n8k16.row.col.f32.bf16.bf16.f32 "       \
        "{%0,%1,%2,%3}, {%4,%5,%6,%7}, {%8,%9}, {%0,%1,%2,%3};"               \
        : "+f"((c)[0]), "+f"((c)[1]), "+f"((c)[2]), "+f"((c)[3])              \
        : "r"((a)[0]), "r"((a)[1]), "r"((a)[2]), "r"((a)[3]), "r"(b0), "r"(b1))

__device__ __forceinline__ float2 bf2f(uint32_t u) {
    __nv_bfloat162 h = *(__nv_bfloat162*)&u;
    return __bfloat1622float2(h);
}

// ================= prep kernels =================
__global__ void k_zero(float* out) {
    int t = blockIdx.x * blockDim.x + threadIdx.x;
    if (t < KCLS * DIM) g_sums[t] = 0.0f;
    if (t < KCLS) g_ccount[t] = 0;
    if (t == 0) out[0] = 0.0f;
}

// normalize rows -> bf16, and append row to its class list (fused k_lists)
__global__ void k_norm(const float* __restrict__ x, const int* __restrict__ labels) {
    int row  = blockIdx.x * 8 + (threadIdx.x >> 5);
    int lane = threadIdx.x & 31;
    const float4* src = (const float4*)(x + (size_t)row * DIM);
    float4 v[4];
    float ss = 0.0f;
#pragma unroll
    for (int q = 0; q < 4; q++) {
        v[q] = src[lane + 32 * q];
        ss += v[q].x * v[q].x + v[q].y * v[q].y + v[q].z * v[q].z + v[q].w * v[q].w;
    }
#pragma unroll
    for (int o = 16; o >= 1; o >>= 1) ss += __shfl_xor_sync(0xffffffffu, ss, o);
    float inv = 1.0f / fmaxf(sqrtf(ss), 1e-12f);
    __nv_bfloat162* dsth = (__nv_bfloat162*)(g_embh + (size_t)row * DIM);
#pragma unroll
    for (int q = 0; q < 4; q++) {
        float4 w = v[q];
        w.x *= inv; w.y *= inv; w.z *= inv; w.w *= inv;
        int i = lane + 32 * q;
        dsth[2 * i]     = __floats2bfloat162_rn(w.x, w.y);
        dsth[2 * i + 1] = __floats2bfloat162_rn(w.z, w.w);
    }
    if (lane == 0) {
        int lab = labels[row];
        int pos = atomicAdd(&g_ccount[lab], 1);
        if (pos < LISTCAP) g_lists[lab * LISTCAP + pos] = row;
    }
}

// class partial sums: grid (KCLS, 8 segments), bf16 gather + fp32 atomics
__global__ void k_csum_part() {
    __shared__ int lst_s[LISTCAP / 8 + 8];
    const int k   = blockIdx.x;
    const int seg = blockIdx.y;
    const int t   = threadIdx.x;              // dims 2t, 2t+1
    const int cnt = g_ccount[k];
    const int s0 = (cnt * seg) >> 3;
    const int s1 = (cnt * (seg + 1)) >> 3;
    const int len = s1 - s0;
    const int* lst = g_lists + k * LISTCAP + s0;
    for (int i = t; i < len; i += 256) lst_s[i] = lst[i];
    __syncthreads();

    float a0 = 0.0f, a1 = 0.0f;
    int m = 0;
    for (; m + 8 <= len; m += 8) {
        uint32_t u[8];
#pragma unroll
        for (int j = 0; j < 8; j++)
            u[j] = *(const uint32_t*)(g_embh + (size_t)lst_s[m + j] * DIM + 2 * t);
#pragma unroll
        for (int j = 0; j < 8; j++) {
            float2 f = bf2f(u[j]);
            a0 += f.x; a1 += f.y;
        }
    }
    for (; m < len; m++) {
        float2 f = bf2f(*(const uint32_t*)(g_embh + (size_t)lst_s[m] * DIM + 2 * t));
        a0 += f.x; a1 += f.y;
    }
    if (len > 0) {
        atomicAdd(&g_sums[k * DIM + 2 * t], a0);
        atomicAdd(&g_sums[k * DIM + 2 * t + 1], a1);
    }
}

// finalize: centroids bf16, counts, ||s||^2
__global__ void k_cfin() {
    int k = blockIdx.x;
    int t = threadIdx.x;
    float a0 = g_sums[k * DIM + t];
    float a1 = g_sums[k * DIM + t + 256];
    float c = (float)g_ccount[k];
    if (t == 0) g_cnt[k] = c;
    float inv = 1.0f / fmaxf(c, 1.0f);
    g_centh[k * DIM + t]       = __float2bfloat16(a0 * inv);
    g_centh[k * DIM + t + 256] = __float2bfloat16(a1 * inv);

    __shared__ float red[256];
    red[t] = a0 * a0 + a1 * a1;
    __syncthreads();
    for (int s = 128; s > 0; s >>= 1) {
        if (t < s) red[t] += red[t + s];
        __syncthreads();
    }
    if (t == 0) g_snorm2[k] = red[0];
}

// ================= main: bf16 mma.sync GEMM + fused LSE + inline own-logit =================
// R6-proven loop structure (per-chunk preload + double buffer); only the epilogue differs.
// dyn smem: [0, 128K) resident A; [128K, 160K) B double buffer; [160K, +512) rowOwn
#define SM_B_OFF   131072
#define SM_OWN_OFF (131072 + 2 * 16384)
#define SMEM_BYTES (SM_OWN_OFF + 1024)

__global__ void __launch_bounds__(256, 1)
k_main_mma(const int* __restrict__ labels,
           const float* __restrict__ wp, const float* __restrict__ bp,
           float* __restrict__ out) {
    extern __shared__ char smem[];
    const uint32_t smA = smem_u32(smem);
    const uint32_t smB = smA + SM_B_OFF;
    float* rowOwn = (float*)(smem + SM_OWN_OFF);

    const int tid = threadIdx.x;
    const int wid = tid >> 5;
    const int l   = tid & 31;
    const int wm  = wid >> 1;        // 0..3 (M)
    const int wn  = wid & 1;         // 0..1 (N half)
    const int block_row = blockIdx.x * 128;

    const float wv = fmaxf(wp[0], 1e-6f);
    const float bv = bp[0];

    // ---- load resident A tile (128 x 512 bf16), 16B chunks, XOR swizzle ----
#pragma unroll
    for (int it = 0; it < 32; it++) {
        uint32_t u = it * 256 + tid;
        uint32_t r = u >> 6, ch = u & 63;
        CP16(smA + r * 1024 + ((ch ^ (r & 7)) << 4),
             g_embh + (size_t)(block_row + r) * DIM + ch * 8);
    }
    CP_COMMIT();

    // ---- per-thread row metadata ----
    int   lab_[2][2];
    float cnt_[2][2], sn_[2][2];
#pragma unroll
    for (int mt = 0; mt < 2; mt++)
#pragma unroll
        for (int h = 0; h < 2; h++) {
            int rr = block_row + wm * 32 + mt * 16 + (l >> 2) + h * 8;
            int lb = labels[rr];
            lab_[mt][h] = lb;
            cnt_[mt][h] = g_cnt[lb];
            sn_[mt][h]  = g_snorm2[lb];
        }

    float run_m[2][2], run_s[2][2];
#pragma unroll
    for (int mt = 0; mt < 2; mt++)
#pragma unroll
        for (int h = 0; h < 2; h++) { run_m[mt][h] = -INFINITY; run_s[mt][h] = 0.0f; }

    for (int chunk = 0; chunk < 4; chunk++) {
        const int c0 = chunk * 128;

        // preload B stage 0 of this chunk
#pragma unroll
        for (int it = 0; it < 4; it++) {
            uint32_t u = it * 256 + tid;
            uint32_t nr = u >> 3, k16 = u & 7;
            CP16(smB + nr * 128 + ((k16 ^ (nr & 7)) << 4),
                 g_centh + (size_t)(c0 + nr) * DIM + k16 * 8);
        }
        CP_COMMIT();

        float acc[2][8][4];
#pragma unroll
        for (int mt = 0; mt < 2; mt++)
#pragma unroll
            for (int nt = 0; nt < 8; nt++)
#pragma unroll
                for (int c = 0; c < 4; c++) acc[mt][nt][c] = 0.0f;

        for (int kb = 0; kb < 8; kb++) {
            const uint32_t buf = (uint32_t)(kb & 1);
            if (kb < 7) {
                const uint32_t nb = buf ^ 1;
#pragma unroll
                for (int it = 0; it < 4; it++) {
                    uint32_t u = it * 256 + tid;
                    uint32_t nr = u >> 3, k16 = u & 7;
                    CP16(smB + nb * 16384 + nr * 128 + ((k16 ^ (nr & 7)) << 4),
                         g_centh + (size_t)(c0 + nr) * DIM + (kb + 1) * 64 + k16 * 8);
                }
                CP_COMMIT();
                CP_WAIT1();
            } else {
                CP_WAIT0();
            }
            __syncthreads();

#pragma unroll
            for (int step = 0; step < 4; step++) {
                uint32_t a[2][4];
#pragma unroll
                for (int mt = 0; mt < 2; mt++) {
                    uint32_t r = wm * 32 + mt * 16 + (l & 15);
                    uint32_t chA = kb * 8 + step * 2 + (l >> 4);
                    LDSM4(a[mt][0], a[mt][1], a[mt][2], a[mt][3],
                          smA + r * 1024 + ((chA ^ (r & 7)) << 4));
                }
                uint32_t bf[8][2];
#pragma unroll
                for (int np = 0; np < 4; np++) {
                    uint32_t n = wn * 64 + np * 16 + (l & 7) + ((l >> 4) & 1) * 8;
                    uint32_t chB = step * 2 + ((l >> 3) & 1);
                    uint32_t r0, r1, r2, r3;
                    LDSM4(r0, r1, r2, r3,
                          smB + buf * 16384 + n * 128 + ((chB ^ (n & 7)) << 4));
                    bf[2 * np][0] = r0;     bf[2 * np][1] = r1;
                    bf[2 * np + 1][0] = r2; bf[2 * np + 1][1] = r3;
                }
#pragma unroll
                for (int mt = 0; mt < 2; mt++)
#pragma unroll
                    for (int nt = 0; nt < 8; nt++)
                        MMA16816(acc[mt][nt], a[mt], bf[nt][0], bf[nt][1]);
            }
            __syncthreads();
        }

        // ---- chunk epilogue: per-row LSE over this warp's 64 cols (inline own-logit) ----
#pragma unroll
        for (int mt = 0; mt < 2; mt++) {
#pragma unroll
            for (int h = 0; h < 2; h++) {
                const int lb = lab_[mt][h];
                float v[16];
                float cm = -INFINITY;
#pragma unroll
                for (int nt = 0; nt < 8; nt++)
#pragma unroll
                    for (int cc = 0; cc < 2; cc++) {
                        int col = c0 + wn * 64 + nt * 8 + ((l & 3) << 1) + cc;
                        float raw = acc[mt][nt][h * 2 + cc];
                        float lg;
                        if (col == lb) {
                            float cnt = cnt_[mt][h];
                            if (cnt > 1.0f) {
                                float tt = raw * cnt;          // e . sums[lab]
                                float denom = cnt - 1.0f;
                                float num = (tt - 1.0f) / denom;
                                float nrm = sqrtf(fmaxf(sn_[mt][h] - 2.0f * tt + 1.0f, 0.0f)) / denom;
                                lg = fmaf(wv, num / fmaxf(nrm, 1e-12f), bv);
                            } else {
                                lg = fmaf(wv, raw, bv);        // singleton: keep cur
                            }
                            rowOwn[wm * 32 + mt * 16 + h * 8 + (l >> 2)] = lg;
                        } else {
                            lg = fmaf(wv, raw, bv);
                        }
                        v[nt * 2 + cc] = lg;
                        cm = fmaxf(cm, lg);
                    }
#pragma unroll
                for (int o = 1; o <= 2; o <<= 1)
                    cm = fmaxf(cm, __shfl_xor_sync(0xffffffffu, cm, o));
                float cs = 0.0f;
#pragma unroll
                for (int j = 0; j < 16; j++) cs += __expf(v[j] - cm);
#pragma unroll
                for (int o = 1; o <= 2; o <<= 1)
                    cs += __shfl_xor_sync(0xffffffffu, cs, o);
                float mo = run_m[mt][h];
                float mn = fmaxf(mo, cm);
                run_s[mt][h] = run_s[mt][h] * __expf(mo - mn) + cs * __expf(cm - mn);
                run_m[mt][h] = mn;
            }
        }
    }

    // ---- merge the two N-half warps per row, compute loss ----
    __syncthreads();
    float* marr = (float*)smem;          // reuse A region (dead now)
    float* sarr = marr + 128;
    if (wn == 0 && (l & 3) == 0) {
#pragma unroll
        for (int mt = 0; mt < 2; mt++)
#pragma unroll
            for (int h = 0; h < 2; h++) {
                int rr = wm * 32 + mt * 16 + h * 8 + (l >> 2);
                marr[rr] = run_m[mt][h];
                sarr[rr] = run_s[mt][h];
            }
    }
    __syncthreads();
    float loss = 0.0f;
    if (wn == 1 && (l & 3) == 0) {
#pragma unroll
        for (int mt = 0; mt < 2; mt++)
#pragma unroll
            for (int h = 0; h < 2; h++) {
                int rr = wm * 32 + mt * 16 + h * 8 + (l >> 2);
                float m0 = marr[rr], s0 = sarr[rr];
                float m1 = run_m[mt][h], s1 = run_s[mt][h];
                float mn = fmaxf(m0, m1);
                float ssum = s0 * __expf(m0 - mn) + s1 * __expf(m1 - mn);
                loss += mn + logf(ssum) - rowOwn[rr];
            }
    }
#pragma unroll
    for (int o = 16; o >= 1; o >>= 1) loss += __shfl_xor_sync(0xffffffffu, loss, o);
    if (wn == 1 && l == 0) atomicAdd(out, loss * (1.0f / (float)NROWS));
}

extern "C" void kernel_launch(void* const* d_in, const int* in_sizes, int n_in,
                              void* d_out, int out_size) {
    const float* emb    = (const float*)d_in[0];
    const int*   labels = (const int*)d_in[1];
    const float* wp     = (const float*)d_in[2];
    const float* bp     = (const float*)d_in[3];
    float* out = (float*)d_out;

    cudaFuncSetAttribute(k_main_mma, cudaFuncAttributeMaxDynamicSharedMemorySize, SMEM_BYTES);

    k_zero<<<(KCLS * DIM) / 256, 256>>>(out);
    k_norm<<<NROWS / 8, 256>>>(emb, labels);
    k_csum_part<<<dim3(KCLS, 8), 256>>>();
    k_cfin<<<KCLS, 256>>>();
    k_main_mma<<<NROWS / 128, 256, SMEM_BYTES>>>(labels, wp, bp, out);
}

// round 17
// speedup vs baseline: 1.3016x; 1.3001x over previous
#include <cuda_runtime.h>
#include <cuda_bf16.h>
#include <math.h>
#include <stdint.h>

#define NROWS 65536
#define DIM   512
#define KCLS  512
#define LISTCAP 768

// -------- scratch (device globals; no runtime allocation) --------
__device__ __nv_bfloat16  g_embh[(size_t)NROWS * DIM];   // normalized embeddings bf16
__device__ float          g_sums[KCLS * DIM];            // per-class sums (fp32, atomic)
__device__ __nv_bfloat16  g_centh[KCLS * DIM];           // centroids bf16 (GEMM B)
__device__ float          g_cnt[KCLS];
__device__ float          g_snorm2[KCLS];
__device__ int            g_ccount[KCLS];
__device__ int            g_lists[KCLS * LISTCAP];

// ================= helpers =================
__device__ __forceinline__ uint32_t smem_u32(const void* p) {
    uint32_t a;
    asm("{ .reg .u64 t; cvta.to.shared.u64 t, %1; cvt.u32.u64 %0, t; }" : "=r"(a) : "l"(p));
    return a;
}
#define CP16(dst, src)  asm volatile("cp.async.cg.shared.global [%0], [%1], 16;" :: "r"(dst), "l"(src) : "memory")
#define CP_COMMIT()     asm volatile("cp.async.commit_group;" ::: "memory")
#define CP_WAIT0()      asm volatile("cp.async.wait_group 0;" ::: "memory")
#define CP_WAIT1()      asm volatile("cp.async.wait_group 1;" ::: "memory")

#define LDSM4(r0, r1, r2, r3, addr)                                           \
    asm volatile("ldmatrix.sync.aligned.m8n8.x4.shared.b16 {%0,%1,%2,%3}, [%4];" \
        : "=r"(r0), "=r"(r1), "=r"(r2), "=r"(r3) : "r"(addr))

#define MMA16816(c, a, b0, b1)                                                \
    asm volatile("mma.sync.aligned.m16n8k16.row.col.f32.bf16.bf16.f32 "       \
        "{%0,%1,%2,%3}, {%4,%5,%6,%7}, {%8,%9}, {%0,%1,%2,%3};"               \
        : "+f"((c)[0]), "+f"((c)[1]), "+f"((c)[2]), "+f"((c)[3])              \
        : "r"((a)[0]), "r"((a)[1]), "r"((a)[2]), "r"((a)[3]), "r"(b0), "r"(b1))

__device__ __forceinline__ float2 bf2f(uint32_t u) {
    __nv_bfloat162 h = *(__nv_bfloat162*)&u;
    return __bfloat1622float2(h);
}

// ================= prep kernels (exact 178.7us baseline) =================
__global__ void k_zero(float* out) {
    int t = blockIdx.x * blockDim.x + threadIdx.x;
    if (t < KCLS * DIM) g_sums[t] = 0.0f;
    if (t < KCLS) g_ccount[t] = 0;
    if (t == 0) out[0] = 0.0f;
}

// normalize rows -> bf16 only
__global__ void k_norm(const float* __restrict__ x) {
    int row  = blockIdx.x * 8 + (threadIdx.x >> 5);
    int lane = threadIdx.x & 31;
    const float4* src = (const float4*)(x + (size_t)row * DIM);
    float4 v[4];
    float ss = 0.0f;
#pragma unroll
    for (int q = 0; q < 4; q++) {
        v[q] = src[lane + 32 * q];
        ss += v[q].x * v[q].x + v[q].y * v[q].y + v[q].z * v[q].z + v[q].w * v[q].w;
    }
#pragma unroll
    for (int o = 16; o >= 1; o >>= 1) ss += __shfl_xor_sync(0xffffffffu, ss, o);
    float inv = 1.0f / fmaxf(sqrtf(ss), 1e-12f);
    __nv_bfloat162* dsth = (__nv_bfloat162*)(g_embh + (size_t)row * DIM);
#pragma unroll
    for (int q = 0; q < 4; q++) {
        float4 w = v[q];
        w.x *= inv; w.y *= inv; w.z *= inv; w.w *= inv;
        int i = lane + 32 * q;
        dsth[2 * i]     = __floats2bfloat162_rn(w.x, w.y);
        dsth[2 * i + 1] = __floats2bfloat162_rn(w.z, w.w);
    }
}

__global__ void k_lists(const int* __restrict__ labels) {
    int i = blockIdx.x * blockDim.x + threadIdx.x;
    if (i < NROWS) {
        int lab = labels[i];
        int pos = atomicAdd(&g_ccount[lab], 1);
        if (pos < LISTCAP) g_lists[lab * LISTCAP + pos] = i;
    }
}

// class partial sums: grid (KCLS, 4 segments), bf16 gather + fp32 atomics
__global__ void k_csum_part() {
    __shared__ int lst_s[LISTCAP / 4 + 8];
    const int k   = blockIdx.x;
    const int seg = blockIdx.y;
    const int t   = threadIdx.x;              // dims 2t, 2t+1
    const int cnt = g_ccount[k];
    const int s0 = (cnt * seg) >> 2;
    const int s1 = (cnt * (seg + 1)) >> 2;
    const int len = s1 - s0;
    const int* lst = g_lists + k * LISTCAP + s0;
    for (int i = t; i < len; i += 256) lst_s[i] = lst[i];
    __syncthreads();

    float a0 = 0.0f, a1 = 0.0f;
    int m = 0;
    for (; m + 8 <= len; m += 8) {
        uint32_t u[8];
#pragma unroll
        for (int j = 0; j < 8; j++)
            u[j] = *(const uint32_t*)(g_embh + (size_t)lst_s[m + j] * DIM + 2 * t);
#pragma unroll
        for (int j = 0; j < 8; j++) {
            float2 f = bf2f(u[j]);
            a0 += f.x; a1 += f.y;
        }
    }
    for (; m < len; m++) {
        float2 f = bf2f(*(const uint32_t*)(g_embh + (size_t)lst_s[m] * DIM + 2 * t));
        a0 += f.x; a1 += f.y;
    }
    if (len > 0) {
        atomicAdd(&g_sums[k * DIM + 2 * t], a0);
        atomicAdd(&g_sums[k * DIM + 2 * t + 1], a1);
    }
}

// finalize: centroids bf16, counts, ||s||^2
__global__ void k_cfin() {
    int k = blockIdx.x;
    int t = threadIdx.x;
    float a0 = g_sums[k * DIM + t];
    float a1 = g_sums[k * DIM + t + 256];
    float c = (float)g_ccount[k];
    if (t == 0) g_cnt[k] = c;
    float inv = 1.0f / fmaxf(c, 1.0f);
    g_centh[k * DIM + t]       = __float2bfloat16(a0 * inv);
    g_centh[k * DIM + t + 256] = __float2bfloat16(a1 * inv);

    __shared__ float red[256];
    red[t] = a0 * a0 + a1 * a1;
    __syncthreads();
    for (int s = 128; s > 0; s >>= 1) {
        if (t < s) red[t] += red[t + s];
        __syncthreads();
    }
    if (t == 0) g_snorm2[k] = red[0];
}

// ================= main: bf16 mma.sync GEMM + fused LSE =================
// Identical hot loop + epilogue register footprint to the 178.7us baseline.
// Label-column raw value is recorded to smem; own-logit math happens ONCE
// per row in the final merge via LSE correction (no extra live state in loop).
#define SM_B_OFF   131072
#define SM_OWN_OFF (131072 + 2 * 16384)
#define SMEM_BYTES (SM_OWN_OFF + 1024)

__global__ void __launch_bounds__(256, 1)
k_main_mma(const int* __restrict__ labels,
           const float* __restrict__ wp, const float* __restrict__ bp,
           float* __restrict__ out) {
    extern __shared__ char smem[];
    const uint32_t smA = smem_u32(smem);
    const uint32_t smB = smA + SM_B_OFF;
    float* rowOwn = (float*)(smem + SM_OWN_OFF);   // raw GEMM value at label col

    const int tid = threadIdx.x;
    const int wid = tid >> 5;
    const int l   = tid & 31;
    const int wm  = wid >> 1;        // 0..3 (M)
    const int wn  = wid & 1;         // 0..1 (N half)
    const int block_row = blockIdx.x * 128;

    const float wv = fmaxf(wp[0], 1e-6f);
    const float bv = bp[0];

    // ---- load resident A tile (128 x 512 bf16), 16B chunks, XOR swizzle ----
#pragma unroll
    for (int it = 0; it < 32; it++) {
        uint32_t u = it * 256 + tid;
        uint32_t r = u >> 6, ch = u & 63;
        CP16(smA + r * 1024 + ((ch ^ (r & 7)) << 4),
             g_embh + (size_t)(block_row + r) * DIM + ch * 8);
    }
    CP_COMMIT();

    // ---- per-thread row labels (only labels live across the loop) ----
    int lab_[2][2];
#pragma unroll
    for (int mt = 0; mt < 2; mt++)
#pragma unroll
        for (int h = 0; h < 2; h++) {
            int rr = block_row + wm * 32 + mt * 16 + (l >> 2) + h * 8;
            lab_[mt][h] = labels[rr];
        }

    float run_m[2][2], run_s[2][2];
#pragma unroll
    for (int mt = 0; mt < 2; mt++)
#pragma unroll
        for (int h = 0; h < 2; h++) { run_m[mt][h] = -INFINITY; run_s[mt][h] = 0.0f; }

    for (int chunk = 0; chunk < 4; chunk++) {
        const int c0 = chunk * 128;

        // preload B stage 0 of this chunk
#pragma unroll
        for (int it = 0; it < 4; it++) {
            uint32_t u = it * 256 + tid;
            uint32_t nr = u >> 3, k16 = u & 7;
            CP16(smB + nr * 128 + ((k16 ^ (nr & 7)) << 4),
                 g_centh + (size_t)(c0 + nr) * DIM + k16 * 8);
        }
        CP_COMMIT();

        float acc[2][8][4];
#pragma unroll
        for (int mt = 0; mt < 2; mt++)
#pragma unroll
            for (int nt = 0; nt < 8; nt++)
#pragma unroll
                for (int c = 0; c < 4; c++) acc[mt][nt][c] = 0.0f;

        for (int kb = 0; kb < 8; kb++) {
            const uint32_t buf = (uint32_t)(kb & 1);
            if (kb < 7) {
                const uint32_t nb = buf ^ 1;
#pragma unroll
                for (int it = 0; it < 4; it++) {
                    uint32_t u = it * 256 + tid;
                    uint32_t nr = u >> 3, k16 = u & 7;
                    CP16(smB + nb * 16384 + nr * 128 + ((k16 ^ (nr & 7)) << 4),
                         g_centh + (size_t)(c0 + nr) * DIM + (kb + 1) * 64 + k16 * 8);
                }
                CP_COMMIT();
                CP_WAIT1();
            } else {
                CP_WAIT0();
            }
            __syncthreads();

#pragma unroll
            for (int step = 0; step < 4; step++) {
                uint32_t a[2][4];
#pragma unroll
                for (int mt = 0; mt < 2; mt++) {
                    uint32_t r = wm * 32 + mt * 16 + (l & 15);
                    uint32_t chA = kb * 8 + step * 2 + (l >> 4);
                    LDSM4(a[mt][0], a[mt][1], a[mt][2], a[mt][3],
                          smA + r * 1024 + ((chA ^ (r & 7)) << 4));
                }
                uint32_t bf[8][2];
#pragma unroll
                for (int np = 0; np < 4; np++) {
                    uint32_t n = wn * 64 + np * 16 + (l & 7) + ((l >> 4) & 1) * 8;
                    uint32_t chB = step * 2 + ((l >> 3) & 1);
                    uint32_t r0, r1, r2, r3;
                    LDSM4(r0, r1, r2, r3,
                          smB + buf * 16384 + n * 128 + ((chB ^ (n & 7)) << 4));
                    bf[2 * np][0] = r0;     bf[2 * np][1] = r1;
                    bf[2 * np + 1][0] = r2; bf[2 * np + 1][1] = r3;
                }
#pragma unroll
                for (int mt = 0; mt < 2; mt++)
#pragma unroll
                    for (int nt = 0; nt < 8; nt++)
                        MMA16816(acc[mt][nt], a[mt], bf[nt][0], bf[nt][1]);
            }
            __syncthreads();
        }

        // ---- chunk epilogue: uniform LSE; record raw label value only ----
#pragma unroll
        for (int mt = 0; mt < 2; mt++) {
#pragma unroll
            for (int h = 0; h < 2; h++) {
                const int lb = lab_[mt][h];
                float v[16];
                float cm = -INFINITY;
#pragma unroll
                for (int nt = 0; nt < 8; nt++)
#pragma unroll
                    for (int cc = 0; cc < 2; cc++) {
                        int col = c0 + wn * 64 + nt * 8 + ((l & 3) << 1) + cc;
                        float raw = acc[mt][nt][h * 2 + cc];
                        if (col == lb)
                            rowOwn[wm * 32 + mt * 16 + h * 8 + (l >> 2)] = raw;
                        float lg = fmaf(wv, raw, bv);
                        v[nt * 2 + cc] = lg;
                        cm = fmaxf(cm, lg);
                    }
#pragma unroll
                for (int o = 1; o <= 2; o <<= 1)
                    cm = fmaxf(cm, __shfl_xor_sync(0xffffffffu, cm, o));
                float cs = 0.0f;
#pragma unroll
                for (int j = 0; j < 16; j++) cs += __expf(v[j] - cm);
#pragma unroll
                for (int o = 1; o <= 2; o <<= 1)
                    cs += __shfl_xor_sync(0xffffffffu, cs, o);
                float mo = run_m[mt][h];
                float mn = fmaxf(mo, cm);
                run_s[mt][h] = run_s[mt][h] * __expf(mo - mn) + cs * __expf(cm - mn);
                run_m[mt][h] = mn;
            }
        }
    }

    // ---- merge halves; apply own-logit LSE correction; loss ----
    __syncthreads();
    float* marr = (float*)smem;          // reuse A region (dead now)
    float* sarr = marr + 128;
    if (wn == 0 && (l & 3) == 0) {
#pragma unroll
        for (int mt = 0; mt < 2; mt++)
#pragma unroll
            for (int h = 0; h < 2; h++) {
                int rr = wm * 32 + mt * 16 + h * 8 + (l >> 2);
                marr[rr] = run_m[mt][h];
                sarr[rr] = run_s[mt][h];
            }
    }
    __syncthreads();
    float loss = 0.0f;
    if (wn == 1 && (l & 3) == 0) {
#pragma unroll
        for (int mt = 0; mt < 2; mt++)
#pragma unroll
            for (int h = 0; h < 2; h++) {
                int rr = wm * 32 + mt * 16 + h * 8 + (l >> 2);
                float m0 = marr[rr], s0 = sarr[rr];
                float m1 = run_m[mt][h], s1 = run_s[mt][h];
                float mn = fmaxf(m0, m1);
                float ssum = s0 * __expf(m0 - mn) + s1 * __expf(m1 - mn);

                // own-logit reconstruction (once per row, cold path)
                int   lb  = lab_[mt][h];
                float raw = rowOwn[rr];
                float x_old = fmaf(wv, raw, bv);
                float cnt = g_cnt[lb];
                float x_new;
                if (cnt > 1.0f) {
                    float tt = raw * cnt;              // e . sums[lab]
                    float denom = cnt - 1.0f;
                    float num = (tt - 1.0f) / denom;
                    float nrm = sqrtf(fmaxf(g_snorm2[lb] - 2.0f * tt + 1.0f, 0.0f)) / denom;
                    x_new = fmaf(wv, num / fmaxf(nrm, 1e-12f), bv);
                } else {
                    x_new = x_old;                     // singleton: keep cur
                }
                ssum += __expf(x_new - mn) - __expf(x_old - mn);
                loss += mn + logf(ssum) - x_new;
            }
    }
#pragma unroll
    for (int o = 16; o >= 1; o >>= 1) loss += __shfl_xor_sync(0xffffffffu, loss, o);
    if (wn == 1 && l == 0) atomicAdd(out, loss * (1.0f / (float)NROWS));
}

extern "C" void kernel_launch(void* const* d_in, const int* in_sizes, int n_in,
                              void* d_out, int out_size) {
    const float* emb    = (const float*)d_in[0];
    const int*   labels = (const int*)d_in[1];
    const float* wp     = (const float*)d_in[2];
    const float* bp     = (const float*)d_in[3];
    float* out = (float*)d_out;

    cudaFuncSetAttribute(k_main_mma, cudaFuncAttributeMaxDynamicSharedMemorySize, SMEM_BYTES);

    k_zero<<<(KCLS * DIM) / 256, 256>>>(out);
    k_norm<<<NROWS / 8, 256>>>(emb);
    k_lists<<<NROWS / 256, 256>>>(labels);
    k_csum_part<<<dim3(KCLS, 4), 256>>>();
    k_cfin<<<KCLS, 256>>>();
    k_main_mma<<<NROWS / 128, 256, SMEM_BYTES>>>(labels, wp, bp, out);
}